// round 8
// baseline (speedup 1.0000x reference)
#include <cuda_runtime.h>

// Water constraint residuals:
//   x: [B=16, N=200000, D=18] fp32  (first 9 floats/row = 3 particles x xyz)
//   l: [3] fp32 bond lengths
//   out: [B, N, 3] fp32 = |r0-r1|-l0, |r1-r2|-l1, |r2-r0|-l2
//
// Coalesced smem staging. Per 4-row "group" (288B), all needed bytes live in
// [0,256) = 16 float4s. A 256-thread block stages 64 groups (256 rows):
// each thread issues 4 fully-coalesced LDG.128 (consecutive lanes ->
// consecutive addresses), cutting L1tex wavefronts ~5x vs strided per-thread
// loads while keeping the identical 8-of-9 DRAM sector footprint.
// Groups are padded to 272B in smem (STS.128 alignment + bank de-aliasing).

#define GROUPS_PER_BLOCK 64
#define SMEM_GROUP_F4    17            // 16 data float4s + 1 pad
#define SMEM_GROUP_F     (SMEM_GROUP_F4 * 4)   // 68 floats

__global__ __launch_bounds__(256) void water_kernel3(
    const float4* __restrict__ x4,     // input viewed as float4 (16B aligned)
    const float* __restrict__ l,
    float* __restrict__ out)
{
    __shared__ float4 sm4[GROUPS_PER_BLOCK * SMEM_GROUP_F4];

    const int tid = threadIdx.x;
    const long long g_base = (long long)blockIdx.x * GROUPS_PER_BLOCK;

    // ---- Stage: 64 groups x 16 float4s = 1024 float4s, 4 per thread.
    // L = tid + 256*i : consecutive lanes -> consecutive j within a group.
    #pragma unroll
    for (int i = 0; i < 4; i++) {
        int L = tid + 256 * i;
        int gl = L >> 4;          // local group 0..63
        int j  = L & 15;          // float4 within group 0..15
        // group stride in global = 288B = 18 float4s
        float4 v = __ldcs(x4 + (g_base + gl) * 18 + j);
        sm4[gl * SMEM_GROUP_F4 + j] = v;
    }
    __syncthreads();

    const float l0 = __ldg(l + 0);
    const float l1 = __ldg(l + 1);
    const float l2 = __ldg(l + 2);

    // ---- Compute: thread t handles row (g_base*4 + t); row k = t%4 of
    // local group t/4. Row floats start at smem word 68*(t/4) + 18*(t%4).
    const float* sm = reinterpret_cast<const float*>(sm4);
    const float* s = sm + (tid >> 2) * SMEM_GROUP_F + (tid & 3) * 18;

    float f0 = s[0], f1 = s[1], f2 = s[2];
    float f3 = s[3], f4 = s[4], f5 = s[5];
    float f6 = s[6], f7 = s[7], f8 = s[8];

    // r0=(f0,f1,f2) r1=(f3,f4,f5) r2=(f6,f7,f8)
    float d0x = f0 - f3, d0y = f1 - f4, d0z = f2 - f5;   // r0 - r1
    float d1x = f3 - f6, d1y = f4 - f7, d1z = f5 - f8;   // r1 - r2
    float d2x = f6 - f0, d2y = f7 - f1, d2z = f8 - f2;   // r2 - r0

    float n0 = sqrtf(fmaf(d0x, d0x, fmaf(d0y, d0y, d0z * d0z)));
    float n1 = sqrtf(fmaf(d1x, d1x, fmaf(d1y, d1y, d1z * d1z)));
    float n2 = sqrtf(fmaf(d2x, d2x, fmaf(d2y, d2y, d2z * d2z)));

    long long row = g_base * 4 + tid;
    float* o = out + row * 3;
    __stcs(o + 0, n0 - l0);
    __stcs(o + 1, n1 - l1);
    __stcs(o + 2, n2 - l2);
}

extern "C" void kernel_launch(void* const* d_in, const int* in_sizes, int n_in,
                              void* d_out, int out_size)
{
    const float4* x4 = (const float4*)d_in[0];
    const float* l = (const float*)d_in[1];
    float* out = (float*)d_out;

    int M = in_sizes[0] / 18;          // 3,200,000 rows (divisible by 256)
    int grid = M / 256;                // 12500 blocks, 256 rows each

    water_kernel3<<<grid, 256>>>(x4, l, out);
}